// round 8
// baseline (speedup 1.0000x reference)
#include <cuda_runtime.h>
#include <cuda_fp16.h>
#include <cstdint>

// CapsuleConv = GEMM (rows=(b,w,a)=130944, K=(k,n,x)=384, cols=(m,d)=128) + fused LayerNorm.
// Single-pass fp16 mma.sync. Occupancy-optimized: CTA tile 64x128, warp tile 32x32,
// single-buffered B (54.4KB smem) -> 4 CTAs/SM, 32 warps/SM.

#define BB    16
#define NIN   32
#define LLEN  2048
#define MMO   32
#define WOUTN 2046

#define WTILE   16          // w per CTA (M = 64 output rows)
#define ASTRIDE 272         // smem row stride bytes (128 fp16 = 256B + 16 pad)
#define A_ROWS  72          // (WTILE + 2) * 4
#define A_MAT   (A_ROWS * ASTRIDE)        // 19584
#define B_MAT   (128 * ASTRIDE)           // 34816
#define OFF_B   A_MAT
#define SMEM_BYTES (A_MAT + B_MAT)        // 54400 -> 4 CTAs/SM
#define SSTRIDE 132         // epilogue fp32 row stride (floats)
#define OUT_SCALE (1.0f / 32.0f)

// ---- persistent scratch: rearranged fp16 weight ----
__device__ __half g_B[3 * 128 * 128];     // B[k][c=m*4+d][n*4+x] = w (unscaled)

// ======================= helpers =======================
__device__ __forceinline__ uint32_t smem_u32(const void* p) {
    uint32_t a;
    asm("{ .reg .u64 t; cvta.to.shared.u64 t, %1; cvt.u32.u64 %0, t; }" : "=r"(a) : "l"(p));
    return a;
}
__device__ __forceinline__ void cp16(uint32_t dst, const void* src) {
    asm volatile("cp.async.cg.shared.global [%0], [%1], 16;" :: "r"(dst), "l"(src));
}
__device__ __forceinline__ void cp_commit() {
    asm volatile("cp.async.commit_group;" ::: "memory");
}
__device__ __forceinline__ void ldsm4(uint32_t* r, uint32_t addr) {
    asm volatile("ldmatrix.sync.aligned.m8n8.x4.shared.b16 {%0,%1,%2,%3}, [%4];"
                 : "=r"(r[0]), "=r"(r[1]), "=r"(r[2]), "=r"(r[3]) : "r"(addr));
}
__device__ __forceinline__ void mma16816(float* d, const uint32_t* a,
                                         uint32_t b0, uint32_t b1) {
    asm volatile(
        "mma.sync.aligned.m16n8k16.row.col.f32.f16.f16.f32 "
        "{%0,%1,%2,%3}, {%4,%5,%6,%7}, {%8,%9}, {%0,%1,%2,%3};"
        : "+f"(d[0]), "+f"(d[1]), "+f"(d[2]), "+f"(d[3])
        : "r"(a[0]), "r"(a[1]), "r"(a[2]), "r"(a[3]), "r"(b0), "r"(b1));
}
__device__ __forceinline__ uint32_t pkh(__half a, __half b) {
    __half2 t(a, b);
    return *reinterpret_cast<uint32_t*>(&t);
}

// ======================= tiny prepass: rearrange + convert weight =======================
__global__ __launch_bounds__(256)
void prep_b(const float* __restrict__ w) {
    const int idx = blockIdx.x * 256 + threadIdx.x;   // < 49152
    const int col = idx & 127;       // n*4+x
    const int row = idx >> 7;
    const int c = row & 127;         // m*4+d
    const int k = row >> 7;
    const int n = col >> 2, xx = col & 3;
    const int m = c >> 2, d = c & 3;
    g_B[idx] = __float2half_rn(w[(((k * NIN + n) * 4 + xx) * 4 + d) * MMO + m]);
}

// ======================= main kernel =======================
__global__ __launch_bounds__(256, 4)
void caps_mma_kernel(const float* __restrict__ x,
                     const float* __restrict__ gamma,
                     const float* __restrict__ beta,
                     float* __restrict__ out) {
    extern __shared__ char dsm[];
    const uint32_t smem = smem_u32(dsm);

    const int tid = threadIdx.x;
    const int wid = tid >> 5, lid = tid & 31;
    const int b  = blockIdx.y;
    const int w0 = blockIdx.x * WTILE;

    const int wm = wid & 1;           // rows wm*32 .. +32
    const int wn = wid >> 1;          // cols wn*32 .. +32
    const uint32_t lane_off = (uint32_t)((lid & 15) * ASTRIDE + (lid >> 4) * 16);

    const float* xb = x + (size_t)b * NIN * LLEN * 16;

    // ---- issue B[0] (2048 cp16, 8/thread) ----
#pragma unroll
    for (int j = 0; j < 8; ++j) {
        const int u = tid + 256 * j;
        const int row = u >> 4, seg = u & 15;
        cp16(smem + OFF_B + (uint32_t)(row * ASTRIDE + seg * 16),
             g_B + (size_t)row * 128 + seg * 8);
    }
    cp_commit();

    // ---- build A tile inline: LDG fp32 -> f2h -> STS (overlaps B cp.async) ----
    // row r = ll*4 + a, col (n*4+xx); one float4 = one (nl, l, a). Coalesced 512B/warp.
    // Part 1: ll in [0,16): l = w0+ll <= 2047, no clamp.
#pragma unroll
    for (int j = 0; j < 8; ++j) {
        const int F  = tid + 256 * j;     // < 2048
        const int a  = F & 3;
        const int ll = (F >> 2) & 15;
        const int nl = F >> 6;
        const float4 v = *reinterpret_cast<const float4*>(
            xb + ((size_t)nl * LLEN + (w0 + ll)) * 16 + a * 4);
        *reinterpret_cast<uint2*>(dsm + (uint32_t)((ll * 4 + a) * ASTRIDE + nl * 8)) =
            make_uint2(pkh(__float2half_rn(v.x), __float2half_rn(v.y)),
                       pkh(__float2half_rn(v.z), __float2half_rn(v.w)));
    }
    // Part 2: ll in {16,17} (overhang; clamp; garbage only for w>=WOUT, never stored)
    {
        const int a  = tid & 3;
        const int ll = 16 + ((tid >> 2) & 1);
        const int nl = tid >> 3;
        int l = w0 + ll; if (l > LLEN - 1) l = LLEN - 1;
        const float4 v = *reinterpret_cast<const float4*>(
            xb + ((size_t)nl * LLEN + l) * 16 + a * 4);
        *reinterpret_cast<uint2*>(dsm + (uint32_t)((ll * 4 + a) * ASTRIDE + nl * 8)) =
            make_uint2(pkh(__float2half_rn(v.x), __float2half_rn(v.y)),
                       pkh(__float2half_rn(v.z), __float2half_rn(v.w)));
    }

    float d[2][4][4];
#pragma unroll
    for (int i = 0; i < 2; i++)
#pragma unroll
        for (int j = 0; j < 4; j++)
#pragma unroll
            for (int q = 0; q < 4; q++) d[i][j][q] = 0.0f;

    for (int k = 0; k < 3; ++k) {
        if (k > 0) {
            __syncthreads();   // all warps done reading B[k-1]
#pragma unroll
            for (int j = 0; j < 8; ++j) {
                const int u = tid + 256 * j;
                const int row = u >> 4, seg = u & 15;
                cp16(smem + OFF_B + (uint32_t)(row * ASTRIDE + seg * 16),
                     g_B + (size_t)(k * 128 + row) * 128 + seg * 8);
            }
            cp_commit();
        }
        asm volatile("cp.async.wait_group 0;" ::: "memory");
        __syncthreads();   // B[k] visible (k==0: A STS also visible)

        const uint32_t sA = smem + (uint32_t)((wm * 32 + 4 * k) * ASTRIDE) + lane_off;
        const uint32_t sB = smem + OFF_B + (uint32_t)(wn * 32 * ASTRIDE) + lane_off;

#pragma unroll
        for (int ks = 0; ks < 8; ++ks) {
            const uint32_t kb = ks * 32;   // k16 step = 32 bytes
            uint32_t Ar[2][4], Br[2][4];
#pragma unroll
            for (int mf = 0; mf < 2; ++mf)
                ldsm4(Ar[mf], sA + (uint32_t)(mf * 16) * ASTRIDE + kb);
#pragma unroll
            for (int bg = 0; bg < 2; ++bg)
                ldsm4(Br[bg], sB + (uint32_t)(bg * 16) * ASTRIDE + kb);
#pragma unroll
            for (int mf = 0; mf < 2; ++mf)
#pragma unroll
                for (int bg = 0; bg < 2; ++bg) {
                    mma16816(d[mf][bg * 2],     Ar[mf], Br[bg][0], Br[bg][2]);
                    mma16816(d[mf][bg * 2 + 1], Ar[mf], Br[bg][1], Br[bg][3]);
                }
        }
    }

    // ---- epilogue: accum -> smem, scale 1/32, fused LayerNorm over (a,d)=16 ----
    __syncthreads();
    float* S = reinterpret_cast<float*>(dsm);   // [64][SSTRIDE]
    const int g = lid >> 2, t4 = lid & 3;
#pragma unroll
    for (int mf = 0; mf < 2; ++mf)
#pragma unroll
        for (int ng = 0; ng < 4; ++ng) {
            const int r = wm * 32 + mf * 16 + g;
            const int c = wn * 32 + ng * 8 + t4 * 2;
            S[r * SSTRIDE + c]           = d[mf][ng][0];
            S[r * SSTRIDE + c + 1]       = d[mf][ng][1];
            S[(r + 8) * SSTRIDE + c]     = d[mf][ng][2];
            S[(r + 8) * SSTRIDE + c + 1] = d[mf][ng][3];
        }
    __syncthreads();

    float gam[16], bet[16];
#pragma unroll
    for (int i = 0; i < 16; i++) { gam[i] = __ldg(gamma + i); bet[i] = __ldg(beta + i); }

    // 512 LN groups (wl 0..15 x m 0..31), 2 per thread
#pragma unroll
    for (int gq = 0; gq < 2; ++gq) {
        const int G  = tid + gq * 256;
        const int wl = G >> 5;
        const int m  = G & 31;
        const int w  = w0 + wl;
        if (w >= WOUTN) continue;

        float vals[16];
#pragma unroll
        for (int a = 0; a < 4; a++) {
            const float4 v = *reinterpret_cast<const float4*>(
                S + (wl * 4 + a) * SSTRIDE + m * 4);
            vals[a * 4 + 0] = v.x * OUT_SCALE; vals[a * 4 + 1] = v.y * OUT_SCALE;
            vals[a * 4 + 2] = v.z * OUT_SCALE; vals[a * 4 + 3] = v.w * OUT_SCALE;
        }
        float mu = 0.0f;
#pragma unroll
        for (int i = 0; i < 16; i++) mu += vals[i];
        mu *= 0.0625f;
        float var = 0.0f;
#pragma unroll
        for (int i = 0; i < 16; i++) {
            const float dv = vals[i] - mu;
            var = fmaf(dv, dv, var);
        }
        var *= 0.0625f;
        const float inv = rsqrtf(var + 1e-5f);

        const size_t base = (((size_t)b * MMO + m) * WOUTN + w) * 16;
#pragma unroll
        for (int q = 0; q < 4; q++) {
            float4 o;
            o.x = fmaf((vals[q * 4 + 0] - mu) * inv, gam[q * 4 + 0], bet[q * 4 + 0]);
            o.y = fmaf((vals[q * 4 + 1] - mu) * inv, gam[q * 4 + 1], bet[q * 4 + 1]);
            o.z = fmaf((vals[q * 4 + 2] - mu) * inv, gam[q * 4 + 2], bet[q * 4 + 2]);
            o.w = fmaf((vals[q * 4 + 3] - mu) * inv, gam[q * 4 + 3], bet[q * 4 + 3]);
            *reinterpret_cast<float4*>(out + base + q * 4) = o;
        }
    }
}

extern "C" void kernel_launch(void* const* d_in, const int* in_sizes, int n_in,
                              void* d_out, int out_size) {
    const float* x     = (const float*)d_in[0];
    const float* w     = (const float*)d_in[1];
    const float* gamma = (const float*)d_in[2];
    const float* beta  = (const float*)d_in[3];
    float* out = (float*)d_out;

    prep_b<<<192, 256>>>(w);

    cudaFuncSetAttribute(caps_mma_kernel,
                         cudaFuncAttributeMaxDynamicSharedMemorySize, SMEM_BYTES);
    dim3 grid(128, BB);   // 128 w-tiles (16 w each) x 16 batches
    caps_mma_kernel<<<grid, 256, SMEM_BYTES>>>(x, gamma, beta, out);
}